// round 3
// baseline (speedup 1.0000x reference)
#include <cuda_runtime.h>
#include <math_constants.h>
#include <stdint.h>

// PQHead: out[b, m*6+d] = codebooks[m, argmax_k <x[b,m*6:...], cb[m,k,:]>, d]
// (forward value of the straight-through estimator == discrete codeword)

#define B_ROWS   32768
#define M_SUB    128
#define HALF_M   64                      // m's per block
#define K_CODES  32
#define D_SUB    6
#define DIM      768
#define RPT      4                       // rows per thread
#define TPB      256                     // 4 row-groups x 64 m
#define TILE_ROWS (RPT * (TPB / HALF_M)) // 16
#define NTILES   (B_ROWS / TILE_ROWS)    // 2048 per half
#define BLK_PER_HALF 296
#define NBLOCKS  (2 * BLK_PER_HALF)      // 592 = 4 per SM, persistent
#define CB_PAIRS (HALF_M * K_CODES * 3)  // 6144 float2 = 48KB

__global__ void __launch_bounds__(TPB, 4)
pq_head_kernel(const float* __restrict__ x,
               const float* __restrict__ cb,
               float* __restrict__ out)
{
    // cbs[(k*3+p)*64 + m] = (cb[mg][k][2p], cb[mg][k][2p+1]), mg = h*64+m
    // 8B lane stride -> conflict-free 64-bit LDS.
    __shared__ float2 cbs[CB_PAIRS];

    const int t = threadIdx.x;
    const int h = blockIdx.x / BLK_PER_HALF;       // which m-half this block owns
    const int bstart = blockIdx.x % BLK_PER_HALF;

    // One-time codebook load for this half (coalesced float2 global reads).
    {
        const float2* cbg = reinterpret_cast<const float2*>(cb) + (size_t)h * HALF_M * 96;
        for (int i = t; i < CB_PAIRS; i += TPB) {
            int mloc = i / 96;          // 96 = K_CODES * 3 pairs per m
            int kp   = i - mloc * 96;
            cbs[kp * HALF_M + mloc] = cbg[(size_t)mloc * 96 + kp];
        }
    }
    __syncthreads();

    const int mloc = t & (HALF_M - 1);
    const int g    = t >> 6;             // row-group 0..3
    const int col0 = (h * HALF_M + mloc) * D_SUB;

    for (int tile = bstart; tile < NTILES; tile += BLK_PER_HALF) {
        const int b0 = tile * TILE_ROWS + g * RPT;

        // Batch-load RPT rows' 6-float subvectors (3x LDG.64 each, front-loaded).
        float xv[RPT][D_SUB];
        #pragma unroll
        for (int r = 0; r < RPT; r++) {
            const float2* p = reinterpret_cast<const float2*>(
                x + (size_t)(b0 + r) * DIM + col0);
            float2 a = p[0], bq = p[1], c = p[2];
            xv[r][0] = a.x;  xv[r][1] = a.y;
            xv[r][2] = bq.x; xv[r][3] = bq.y;
            xv[r][4] = c.x;  xv[r][5] = c.y;
        }

        float best[RPT];
        int   idx[RPT];
        #pragma unroll
        for (int r = 0; r < RPT; r++) { best[r] = -CUDART_INF_F; idx[r] = 0; }

        #pragma unroll
        for (int k = 0; k < K_CODES; k++) {
            const float2 c01 = cbs[(k * 3 + 0) * HALF_M + mloc];
            const float2 c23 = cbs[(k * 3 + 1) * HALF_M + mloc];
            const float2 c45 = cbs[(k * 3 + 2) * HALF_M + mloc];
            #pragma unroll
            for (int r = 0; r < RPT; r++) {
                float dot = xv[r][0] * c01.x;
                dot = fmaf(xv[r][1], c01.y, dot);
                dot = fmaf(xv[r][2], c23.x, dot);
                dot = fmaf(xv[r][3], c23.y, dot);
                dot = fmaf(xv[r][4], c45.x, dot);
                dot = fmaf(xv[r][5], c45.y, dot);
                // EXACT argmax; strict '>' keeps the FIRST max (jnp tie rule).
                bool p = dot > best[r];
                best[r] = p ? dot : best[r];
                idx[r]  = p ? k   : idx[r];
            }
        }

        // Emit the winning codeword rows.
        #pragma unroll
        for (int r = 0; r < RPT; r++) {
            const float2 o01 = cbs[(idx[r] * 3 + 0) * HALF_M + mloc];
            const float2 o23 = cbs[(idx[r] * 3 + 1) * HALF_M + mloc];
            const float2 o45 = cbs[(idx[r] * 3 + 2) * HALF_M + mloc];
            float2* po = reinterpret_cast<float2*>(
                out + (size_t)(b0 + r) * DIM + col0);
            po[0] = o01;
            po[1] = o23;
            po[2] = o45;
        }
    }
}

extern "C" void kernel_launch(void* const* d_in, const int* in_sizes, int n_in,
                              void* d_out, int out_size)
{
    const float* x  = (const float*)d_in[0];
    const float* cb = (const float*)d_in[1];
    float* out      = (float*)d_out;

    pq_head_kernel<<<NBLOCKS, TPB>>>(x, cb, out);
}

// round 4
// speedup vs baseline: 1.0911x; 1.0911x over previous
#include <cuda_runtime.h>
#include <math_constants.h>
#include <stdint.h>

// PQHead: out[b, m*6+d] = codebooks[m, argmax_k <x[b,m*6:...], cb[m,k,:]>, d]
// (forward value of the straight-through estimator == discrete codeword)
//
// Dot accumulation order is FROZEN (x0*c0 then fmaf chain 1..5): this order
// produced ZERO argmax flips vs the JAX reference (rel_err at the reference's
// own cancellation floor). Any reassociation risks ~1e-3 per flipped row.

#define B_ROWS   32768
#define M_SUB    128
#define HALF_M   64                      // m's per block
#define K_CODES  32
#define D_SUB    6
#define DIM      768
#define RPT      2                       // rows per thread (fits 64-reg cap, NO spills)
#define TPB      256                     // 4 row-groups x 64 m
#define TILE_ROWS (RPT * (TPB / HALF_M)) // 8
#define NTILES   (B_ROWS / TILE_ROWS)    // 4096 per half
#define BLK_PER_HALF 296
#define NBLOCKS  (2 * BLK_PER_HALF)      // 592 = 4 per SM, persistent
#define CB_PAIRS (HALF_M * K_CODES * 3)  // 6144 float2 = 48KB

__global__ void __launch_bounds__(TPB, 4)
pq_head_kernel(const float* __restrict__ x,
               const float* __restrict__ cb,
               float* __restrict__ out)
{
    // cbs[(k*3+p)*64 + m] = (cb[mg][k][2p], cb[mg][k][2p+1]), mg = h*64+m
    // 8B lane stride -> conflict-free 64-bit LDS.
    __shared__ float2 cbs[CB_PAIRS];

    const int t = threadIdx.x;
    const int h = blockIdx.x / BLK_PER_HALF;       // which m-half this block owns
    const int bstart = blockIdx.x % BLK_PER_HALF;

    // One-time codebook load for this half (coalesced float2 global reads).
    {
        const float2* cbg = reinterpret_cast<const float2*>(cb) + (size_t)h * HALF_M * 96;
        for (int i = t; i < CB_PAIRS; i += TPB) {
            int mloc = i / 96;          // 96 = K_CODES * 3 pairs per m
            int kp   = i - mloc * 96;
            cbs[kp * HALF_M + mloc] = cbg[(size_t)mloc * 96 + kp];
        }
    }
    __syncthreads();

    const int mloc = t & (HALF_M - 1);
    const int g    = t >> 6;             // row-group 0..3
    const int col0 = (h * HALF_M + mloc) * D_SUB;

    for (int tile = bstart; tile < NTILES; tile += BLK_PER_HALF) {
        const int b0 = tile * TILE_ROWS + g * RPT;

        // Batch-load RPT rows' 6-float subvectors (3x LDG.64 each, front-loaded).
        float xv[RPT][D_SUB];
        #pragma unroll
        for (int r = 0; r < RPT; r++) {
            const float2* p = reinterpret_cast<const float2*>(
                x + (size_t)(b0 + r) * DIM + col0);
            float2 a = p[0], bq = p[1], c = p[2];
            xv[r][0] = a.x;  xv[r][1] = a.y;
            xv[r][2] = bq.x; xv[r][3] = bq.y;
            xv[r][4] = c.x;  xv[r][5] = c.y;
        }

        float best[RPT];
        int   idx[RPT];
        #pragma unroll
        for (int r = 0; r < RPT; r++) { best[r] = -CUDART_INF_F; idx[r] = 0; }

        #pragma unroll
        for (int k = 0; k < K_CODES; k++) {
            const float2 c01 = cbs[(k * 3 + 0) * HALF_M + mloc];
            const float2 c23 = cbs[(k * 3 + 1) * HALF_M + mloc];
            const float2 c45 = cbs[(k * 3 + 2) * HALF_M + mloc];
            #pragma unroll
            for (int r = 0; r < RPT; r++) {
                float dot = xv[r][0] * c01.x;
                dot = fmaf(xv[r][1], c01.y, dot);
                dot = fmaf(xv[r][2], c23.x, dot);
                dot = fmaf(xv[r][3], c23.y, dot);
                dot = fmaf(xv[r][4], c45.x, dot);
                dot = fmaf(xv[r][5], c45.y, dot);
                // EXACT argmax; strict '>' keeps the FIRST max (jnp tie rule).
                bool p = dot > best[r];
                best[r] = p ? dot : best[r];
                idx[r]  = p ? k   : idx[r];
            }
        }

        // Emit the winning codeword rows.
        #pragma unroll
        for (int r = 0; r < RPT; r++) {
            const float2 o01 = cbs[(idx[r] * 3 + 0) * HALF_M + mloc];
            const float2 o23 = cbs[(idx[r] * 3 + 1) * HALF_M + mloc];
            const float2 o45 = cbs[(idx[r] * 3 + 2) * HALF_M + mloc];
            float2* po = reinterpret_cast<float2*>(
                out + (size_t)(b0 + r) * DIM + col0);
            po[0] = o01;
            po[1] = o23;
            po[2] = o45;
        }
    }
}

extern "C" void kernel_launch(void* const* d_in, const int* in_sizes, int n_in,
                              void* d_out, int out_size)
{
    const float* x  = (const float*)d_in[0];
    const float* cb = (const float*)d_in[1];
    float* out      = (float*)d_out;

    pq_head_kernel<<<NBLOCKS, TPB>>>(x, cb, out);
}

// round 5
// speedup vs baseline: 5.7581x; 5.2775x over previous
#include <cuda_runtime.h>
#include <math_constants.h>
#include <stdint.h>

// PQHead: out[b, m*6+d] = codebooks[m, argmax_k <x[b,m*6:...], cb[m,k,:]>, d]
// (forward value of the straight-through estimator == discrete codeword)
//
// FROZEN: dot accumulation order (x0*c0 then fmaf 1..5) and exact predicated
// argmax with strict '>' (first-max tie rule). This combination produced ZERO
// argmax flips vs the JAX reference. No reassociation, no mantissa tricks.
//
// CONFIG LESSONS (R3/R4): a 64-reg cap + 192KB smem/SM forces spills into a
// 36KB L1D -> 8x DRAM traffic, issue 15%. Use 3 CTAs/SM (85-reg budget,
// 144KB smem) and bound k-loop unrolling to keep the live set under the cap.

#define B_ROWS   32768
#define M_SUB    128
#define HALF_M   64                      // m's per block
#define K_CODES  32
#define D_SUB    6
#define DIM      768
#define RPT      4                       // rows per thread
#define TPB      256                     // 4 row-groups x 64 m
#define TILE_ROWS (RPT * (TPB / HALF_M)) // 16
#define NTILES   (B_ROWS / TILE_ROWS)    // 2048 per half
#define BLK_PER_HALF 222                 // 3 blocks/SM total (148*3/2)
#define NBLOCKS  (2 * BLK_PER_HALF)      // 444
#define CB_PAIRS (HALF_M * K_CODES * 3)  // 6144 float2 = 48KB

__global__ void __launch_bounds__(TPB, 3)
pq_head_kernel(const float* __restrict__ x,
               const float* __restrict__ cb,
               float* __restrict__ out)
{
    // cbs[(k*3+p)*64 + m] = (cb[mg][k][2p], cb[mg][k][2p+1]), mg = h*64+m
    // 8B lane stride -> conflict-free 64-bit LDS.
    __shared__ float2 cbs[CB_PAIRS];

    const int t = threadIdx.x;
    const int h = blockIdx.x / BLK_PER_HALF;       // which m-half this block owns
    const int bstart = blockIdx.x % BLK_PER_HALF;

    // One-time codebook load for this half (coalesced float2 global reads).
    {
        const float2* cbg = reinterpret_cast<const float2*>(cb) + (size_t)h * HALF_M * 96;
        for (int i = t; i < CB_PAIRS; i += TPB) {
            int mloc = i / 96;          // 96 = K_CODES * 3 pairs per m
            int kp   = i - mloc * 96;
            cbs[kp * HALF_M + mloc] = cbg[(size_t)mloc * 96 + kp];
        }
    }
    __syncthreads();

    const int mloc = t & (HALF_M - 1);
    const int g    = t >> 6;             // row-group 0..3
    const int col0 = (h * HALF_M + mloc) * D_SUB;

    for (int tile = bstart; tile < NTILES; tile += BLK_PER_HALF) {
        const int b0 = tile * TILE_ROWS + g * RPT;

        // Batch-load RPT rows' 6-float subvectors (3x LDG.64 each, front-loaded).
        float xv[RPT][D_SUB];
        #pragma unroll
        for (int r = 0; r < RPT; r++) {
            const float2* p = reinterpret_cast<const float2*>(
                x + (size_t)(b0 + r) * DIM + col0);
            float2 a = p[0], bq = p[1], c = p[2];
            xv[r][0] = a.x;  xv[r][1] = a.y;
            xv[r][2] = bq.x; xv[r][3] = bq.y;
            xv[r][4] = c.x;  xv[r][5] = c.y;
        }

        float best[RPT];
        int   idx[RPT];
        #pragma unroll
        for (int r = 0; r < RPT; r++) { best[r] = -CUDART_INF_F; idx[r] = 0; }

        // Bounded unroll: limits LDS hoisting so the live set fits 85 regs.
        #pragma unroll 4
        for (int k = 0; k < K_CODES; k++) {
            const float2 c01 = cbs[(k * 3 + 0) * HALF_M + mloc];
            const float2 c23 = cbs[(k * 3 + 1) * HALF_M + mloc];
            const float2 c45 = cbs[(k * 3 + 2) * HALF_M + mloc];
            #pragma unroll
            for (int r = 0; r < RPT; r++) {
                float dot = xv[r][0] * c01.x;
                dot = fmaf(xv[r][1], c01.y, dot);
                dot = fmaf(xv[r][2], c23.x, dot);
                dot = fmaf(xv[r][3], c23.y, dot);
                dot = fmaf(xv[r][4], c45.x, dot);
                dot = fmaf(xv[r][5], c45.y, dot);
                // EXACT argmax; strict '>' keeps the FIRST max (jnp tie rule).
                bool p = dot > best[r];
                best[r] = p ? dot : best[r];
                idx[r]  = p ? k   : idx[r];
            }
        }

        // Emit the winning codeword rows.
        #pragma unroll
        for (int r = 0; r < RPT; r++) {
            const float2 o01 = cbs[(idx[r] * 3 + 0) * HALF_M + mloc];
            const float2 o23 = cbs[(idx[r] * 3 + 1) * HALF_M + mloc];
            const float2 o45 = cbs[(idx[r] * 3 + 2) * HALF_M + mloc];
            float2* po = reinterpret_cast<float2*>(
                out + (size_t)(b0 + r) * DIM + col0);
            po[0] = o01;
            po[1] = o23;
            po[2] = o45;
        }
    }
}

extern "C" void kernel_launch(void* const* d_in, const int* in_sizes, int n_in,
                              void* d_out, int out_size)
{
    const float* x  = (const float*)d_in[0];
    const float* cb = (const float*)d_in[1];
    float* out      = (float*)d_out;

    pq_head_kernel<<<NBLOCKS, TPB>>>(x, cb, out);
}

// round 6
// speedup vs baseline: 6.0508x; 1.0508x over previous
#include <cuda_runtime.h>
#include <math_constants.h>
#include <stdint.h>

// PQHead: out[b, m*6+d] = codebooks[m, argmax_k <x[b,m*6:...], cb[m,k,:]>, d]
// (forward value of the straight-through estimator == discrete codeword)
//
// FROZEN: dot accumulation order (x0*c0 then fmaf 1..5) and exact predicated
// argmax with strict '>' (first-max tie rule). Zero argmax flips vs reference.
//
// CONFIG LESSONS:
//  R3/R4: reg cap + FULL k-unroll -> spills -> 8x DRAM traffic, issue 15%.
//  R5: unroll-4 bound -> 61 regs, no spills, 68us, issue 60.9% @ 24 warps/SM.
//  R6: quarter-split codebook (24KB/CTA) -> 4 CTAs/SM = 32 warps, cap 64 regs
//      is safe because the bounded unroll needs only 61.

#define B_ROWS   32768
#define M_SUB    128
#define QM       32                      // m's per block (quarter split)
#define K_CODES  32
#define D_SUB    6
#define DIM      768
#define RPT      4                       // rows per thread
#define TPB      256                     // 8 row-groups x 32 m
#define TILE_ROWS (RPT * (TPB / QM))     // 32
#define NTILES   (B_ROWS / TILE_ROWS)    // 1024 per quarter
#define BLK_PER_Q 148                    // 4 blocks/SM total
#define NBLOCKS  (4 * BLK_PER_Q)         // 592
#define CB_PAIRS (QM * K_CODES * 3)      // 3072 float2 = 24KB

__global__ void __launch_bounds__(TPB, 4)
pq_head_kernel(const float* __restrict__ x,
               const float* __restrict__ cb,
               float* __restrict__ out)
{
    // cbs[(k*3+p)*32 + m] = (cb[mg][k][2p], cb[mg][k][2p+1]), mg = q*32+m
    // 8B lane stride over 32 lanes -> conflict-free 64-bit LDS.
    __shared__ float2 cbs[CB_PAIRS];

    const int t = threadIdx.x;
    const int q = blockIdx.x / BLK_PER_Q;        // which m-quarter this block owns
    const int bstart = blockIdx.x % BLK_PER_Q;

    // One-time codebook load for this quarter (coalesced float2 global reads).
    {
        const float2* cbg = reinterpret_cast<const float2*>(cb) + (size_t)q * QM * 96;
        for (int i = t; i < CB_PAIRS; i += TPB) {
            int mloc = i / 96;          // 96 = K_CODES * 3 pairs per m
            int kp   = i - mloc * 96;
            cbs[kp * QM + mloc] = cbg[(size_t)mloc * 96 + kp];
        }
    }
    __syncthreads();

    const int mloc = t & (QM - 1);
    const int g    = t >> 5;             // row-group 0..7
    const int col0 = (q * QM + mloc) * D_SUB;

    for (int tile = bstart; tile < NTILES; tile += BLK_PER_Q) {
        const int b0 = tile * TILE_ROWS + g * RPT;

        // Batch-load RPT rows' 6-float subvectors (3x LDG.64 each, front-loaded).
        float xv[RPT][D_SUB];
        #pragma unroll
        for (int r = 0; r < RPT; r++) {
            const float2* p = reinterpret_cast<const float2*>(
                x + (size_t)(b0 + r) * DIM + col0);
            float2 a = p[0], bq = p[1], c = p[2];
            xv[r][0] = a.x;  xv[r][1] = a.y;
            xv[r][2] = bq.x; xv[r][3] = bq.y;
            xv[r][4] = c.x;  xv[r][5] = c.y;
        }

        float best[RPT];
        int   idx[RPT];
        #pragma unroll
        for (int r = 0; r < RPT; r++) { best[r] = -CUDART_INF_F; idx[r] = 0; }

        // Bounded unroll: limits LDS hoisting so the live set stays ~61 regs.
        #pragma unroll 4
        for (int k = 0; k < K_CODES; k++) {
            const float2 c01 = cbs[(k * 3 + 0) * QM + mloc];
            const float2 c23 = cbs[(k * 3 + 1) * QM + mloc];
            const float2 c45 = cbs[(k * 3 + 2) * QM + mloc];
            #pragma unroll
            for (int r = 0; r < RPT; r++) {
                float dot = xv[r][0] * c01.x;
                dot = fmaf(xv[r][1], c01.y, dot);
                dot = fmaf(xv[r][2], c23.x, dot);
                dot = fmaf(xv[r][3], c23.y, dot);
                dot = fmaf(xv[r][4], c45.x, dot);
                dot = fmaf(xv[r][5], c45.y, dot);
                // EXACT argmax; strict '>' keeps the FIRST max (jnp tie rule).
                bool p = dot > best[r];
                best[r] = p ? dot : best[r];
                idx[r]  = p ? k   : idx[r];
            }
        }

        // Emit the winning codeword rows.
        #pragma unroll
        for (int r = 0; r < RPT; r++) {
            const float2 o01 = cbs[(idx[r] * 3 + 0) * QM + mloc];
            const float2 o23 = cbs[(idx[r] * 3 + 1) * QM + mloc];
            const float2 o45 = cbs[(idx[r] * 3 + 2) * QM + mloc];
            float2* po = reinterpret_cast<float2*>(
                out + (size_t)(b0 + r) * DIM + col0);
            po[0] = o01;
            po[1] = o23;
            po[2] = o45;
        }
    }
}

extern "C" void kernel_launch(void* const* d_in, const int* in_sizes, int n_in,
                              void* d_out, int out_size)
{
    const float* x  = (const float*)d_in[0];
    const float* cb = (const float*)d_in[1];
    float* out      = (float*)d_out;

    pq_head_kernel<<<NBLOCKS, TPB>>>(x, cb, out);
}